// round 2
// baseline (speedup 1.0000x reference)
#include <cuda_runtime.h>
#include <cuda_bf16.h>

// Problem constants
#define NB   32
#define RESO 256
#define KP   1024
#define FEPS 1e-6f
// -log2(e) / T  with T = 1.0
#define NEG_L2E (-1.44269504088896340736f)
#define LN2F     (0.69314718055994530942f)

// Scratch (allocation-free rule: __device__ globals)
__device__ float2 g_src_c[NB * KP];
__device__ float2 g_trg_c[NB * KP];
__device__ float  g_w2[NB * KP];      // 2 * vis * wt, premultiplied
__device__ float  g_loss_acc;
__device__ float  g_vis_acc;
__device__ int    g_vis_mode;         // 0 = uint8, 1 = int32, 2 = float32

__device__ __forceinline__ float fsqrt_ap(float x) {
    float r; asm("sqrt.approx.f32 %0, %1;" : "=f"(r) : "f"(x)); return r;
}
__device__ __forceinline__ float fex2_ap(float x) {
    float r; asm("ex2.approx.f32 %0, %1;" : "=f"(r) : "f"(x)); return r;
}
__device__ __forceinline__ float flg2_ap(float x) {
    float r; asm("lg2.approx.f32 %0, %1;" : "=f"(r) : "f"(x)); return r;
}

// ---------------------------------------------------------------------------
// Kernel 0: detect kp_vis storage dtype by nonzero-byte pattern per i%4
// residue over the first NB*KP bytes (safe for any candidate dtype).
// uint8 bool : all residues nonzero    -> mode 0
// int32 0/1  : only residue 0 nonzero  -> mode 1
// float 0/1  : residues 2,3 nonzero    -> mode 2
// Also zeroes the accumulators.
// ---------------------------------------------------------------------------
__global__ void detect_kernel(const unsigned char* __restrict__ vis) {
    __shared__ int cnt[4];
    int tid = threadIdx.x;
    if (tid < 4) cnt[tid] = 0;
    __syncthreads();
    int local = 0;
    // stride 256 is 0 mod 4, so residue is constant per thread
    for (int i = tid; i < NB * KP; i += 256)
        if (vis[i]) local++;
    atomicAdd(&cnt[tid & 3], local);
    __syncthreads();
    if (tid == 0) {
        int c0 = cnt[0], c1 = cnt[1], c2 = cnt[2], c3 = cnt[3];
        int mode;
        if (c0 > 0 && c1 == 0 && c2 == 0 && c3 == 0)       mode = 1; // int32
        else if (c0 == 0 && c1 == 0 && (c2 > 0 || c3 > 0)) mode = 2; // float32
        else                                               mode = 0; // uint8
        g_vis_mode = mode;
        g_loss_acc = 0.f;
        g_vis_acc  = 0.f;
    }
}

// Bilinear sample with zero padding, align_corners=True pixel coords.
__device__ __forceinline__ float2 bilin(const float2* __restrict__ flow, float x, float y) {
    float x0f = floorf(x), y0f = floorf(y);
    int   x0  = (int)x0f,  y0  = (int)y0f;
    float wx = x - x0f, wy = y - y0f;
    float ax = 0.f, ay = 0.f;
#pragma unroll
    for (int dy = 0; dy < 2; dy++) {
#pragma unroll
        for (int dx = 0; dx < 2; dx++) {
            int xi = x0 + dx, yi = y0 + dy;
            float w = (dx ? wx : 1.f - wx) * (dy ? wy : 1.f - wy);
            if (xi >= 0 && xi < RESO && yi >= 0 && yi < RESO) {
                float2 v = __ldg(&flow[yi * RESO + xi]);
                ax = fmaf(w, v.x, ax);
                ay = fmaf(w, v.y, ay);
            }
        }
    }
    return make_float2(ax, ay);
}

// ---------------------------------------------------------------------------
// Kernel 1: bilinear sampling + vis decode + premultiplied weights.
// ---------------------------------------------------------------------------
__global__ void sample_kernel(const float* __restrict__ src_flow,
                              const float* __restrict__ trg_flow,
                              const float* __restrict__ src_kp,
                              const float* __restrict__ trg_kp,
                              const void*  __restrict__ kp_vis,
                              const float* __restrict__ kp_wt) {
    int idx = blockIdx.x * blockDim.x + threadIdx.x;
    if (idx >= NB * KP) return;
    int n = idx / KP;
    const float2* sf = (const float2*)src_flow + (size_t)n * RESO * RESO;
    const float2* tf = (const float2*)trg_flow + (size_t)n * RESO * RESO;
    float sx = src_kp[idx * 2 + 0], sy = src_kp[idx * 2 + 1];
    float tx = trg_kp[idx * 2 + 0], ty = trg_kp[idx * 2 + 1];
    g_src_c[idx] = bilin(sf, sx, sy);
    g_trg_c[idx] = bilin(tf, tx, ty);

    int mode = g_vis_mode;
    float vv;
    if (mode == 0)      vv = ((const unsigned char*)kp_vis)[idx] ? 1.f : 0.f;
    else if (mode == 1) vv = ((const int*)kp_vis)[idx] ? 1.f : 0.f;
    else                vv = (((const float*)kp_vis)[idx] != 0.f) ? 1.f : 0.f;

    g_w2[idx] = 2.f * vv * kp_wt[idx];

    // warp-reduce vis count, one atomic per warp
#pragma unroll
    for (int off = 16; off; off >>= 1)
        vv += __shfl_down_sync(0xffffffff, vv, off);
    if ((threadIdx.x & 31) == 0)
        atomicAdd(&g_vis_acc, vv);
}

// ---------------------------------------------------------------------------
// Kernel 2: per-column logsumexp + CE, weighted accumulate.
// grid = (KP/128, NB), block = 256 (128 columns x 2 i-splits)
// ---------------------------------------------------------------------------
__global__ void __launch_bounds__(256)
loss_kernel() {
    __shared__ float2 s_src[KP];      // 8 KB
    __shared__ float  s_part[256];    // 1 KB
    __shared__ float  s_c[8];

    int n   = blockIdx.y;
    int jt  = blockIdx.x;
    int tid = threadIdx.x;

    const float2* src = g_src_c + n * KP;
    for (int i = tid; i < KP; i += 256) s_src[i] = src[i];
    __syncthreads();

    int jl    = tid & 127;
    int split = tid >> 7;
    int j     = jt * 128 + jl;

    float2 t  = g_trg_c[n * KP + j];
    float txe = t.x - FEPS;   // dx = sx - tx + eps = sx - (tx - eps)
    float tye = t.y - FEPS;

    float S  = 0.f;
    int   i0 = split * (KP / 2);
#pragma unroll 8
    for (int i = i0; i < i0 + KP / 2; i++) {
        float2 s = s_src[i];
        float dx = s.x - txe;
        float dy = s.y - tye;
        float d2 = fmaf(dy, dy, dx * dx);
        float d  = fsqrt_ap(d2);
        S += fex2_ap(NEG_L2E * d);
    }
    s_part[tid] = S;
    __syncthreads();

    float contrib = 0.f;
    if (split == 0) {
        float Stot = s_part[jl] + s_part[jl + 128];
        float2 sj  = s_src[j];
        float dxj  = sj.x - txe;
        float dyj  = sj.y - tye;
        float djj  = fsqrt_ap(fmaf(dyj, dyj, dxj * dxj));
        // ce_j = ln(S) + dist_jj / T ; forward d1 == d2 -> factor 2 in g_w2
        float ce = flg2_ap(Stot) * LN2F + djj;
        contrib = ce * g_w2[n * KP + j];
    }

    // block reduction
#pragma unroll
    for (int off = 16; off; off >>= 1)
        contrib += __shfl_down_sync(0xffffffff, contrib, off);
    int w = tid >> 5, l = tid & 31;
    if (l == 0) s_c[w] = contrib;
    __syncthreads();
    if (tid == 0) {
        float c = 0.f;
#pragma unroll
        for (int k = 0; k < 8; k++) c += s_c[k];
        atomicAdd(&g_loss_acc, c);
    }
}

__global__ void finalize_kernel(float* __restrict__ out) {
    out[0] = g_loss_acc / g_vis_acc;
}

extern "C" void kernel_launch(void* const* d_in, const int* in_sizes, int n_in,
                              void* d_out, int out_size) {
    const float* src_flow = (const float*)d_in[0];
    const float* trg_flow = (const float*)d_in[1];
    const float* src_kp   = (const float*)d_in[2];
    const float* trg_kp   = (const float*)d_in[3];
    const void*  kp_vis   = d_in[4];
    const float* kp_wt    = (const float*)d_in[5];
    float* out = (float*)d_out;

    detect_kernel<<<1, 256>>>((const unsigned char*)kp_vis);
    sample_kernel<<<(NB * KP + 255) / 256, 256>>>(src_flow, trg_flow, src_kp,
                                                  trg_kp, kp_vis, kp_wt);
    dim3 grid(KP / 128, NB);
    loss_kernel<<<grid, 256>>>();
    finalize_kernel<<<1, 1>>>(out);
}

// round 3
// speedup vs baseline: 1.3843x; 1.3843x over previous
#include <cuda_runtime.h>
#include <cuda_bf16.h>

// Problem constants
#define NB   32
#define RESO 256
#define KP   1024
#define FEPS 1e-6f
#define NEG_L2E (-1.44269504088896340736f)   // -log2(e)/T, T=1
#define LN2F     (0.69314718055994530942f)

#define LOSS_BLOCKS (NB * (KP / 128))        // 256

// Scratch (allocation-free rule: __device__ globals)
__device__ float2 g_src_c[NB * KP];
__device__ float2 g_trg_c[NB * KP];
__device__ float  g_loss_acc;
__device__ float  g_vis_acc;
__device__ int    g_vis_mode;                // 0 = uint8, 1 = int32, 2 = float32
__device__ unsigned int g_done = 0;

__device__ __forceinline__ float fsqrt_ap(float x) {
    float r; asm("sqrt.approx.f32 %0, %1;" : "=f"(r) : "f"(x)); return r;
}
__device__ __forceinline__ float fex2_ap(float x) {
    float r; asm("ex2.approx.f32 %0, %1;" : "=f"(r) : "f"(x)); return r;
}
__device__ __forceinline__ float flg2_ap(float x) {
    float r; asm("lg2.approx.f32 %0, %1;" : "=f"(r) : "f"(x)); return r;
}
// packed f32x2 add: (a.x+b.x, a.y+b.y) in one instruction
__device__ __forceinline__ float2 fadd2(float2 a, float2 b) {
    unsigned long long ra, rb, rc;
    asm("mov.b64 %0, {%1, %2};" : "=l"(ra) : "f"(a.x), "f"(a.y));
    asm("mov.b64 %0, {%1, %2};" : "=l"(rb) : "f"(b.x), "f"(b.y));
    asm("add.rn.f32x2 %0, %1, %2;" : "=l"(rc) : "l"(ra), "l"(rb));
    float2 c;
    asm("mov.b64 {%0, %1}, %2;" : "=f"(c.x), "=f"(c.y) : "l"(rc));
    return c;
}

// Bilinear sample with zero padding, align_corners=True pixel coords.
__device__ __forceinline__ float2 bilin(const float2* __restrict__ flow, float x, float y) {
    float x0f = floorf(x), y0f = floorf(y);
    int   x0  = (int)x0f,  y0  = (int)y0f;
    float wx = x - x0f, wy = y - y0f;
    float ax = 0.f, ay = 0.f;
#pragma unroll
    for (int dy = 0; dy < 2; dy++) {
#pragma unroll
        for (int dx = 0; dx < 2; dx++) {
            int xi = x0 + dx, yi = y0 + dy;
            float w = (dx ? wx : 1.f - wx) * (dy ? wy : 1.f - wy);
            if (xi >= 0 && xi < RESO && yi >= 0 && yi < RESO) {
                float2 v = __ldg(&flow[yi * RESO + xi]);
                ax = fmaf(w, v.x, ax);
                ay = fmaf(w, v.y, ay);
            }
        }
    }
    return make_float2(ax, ay);
}

// ---------------------------------------------------------------------------
// Kernel 1 (fused): blocks 0..127 do bilinear sampling; block 128 detects the
// kp_vis storage dtype (byte pattern per i%4 over the first NB*KP bytes, safe
// for every candidate dtype) and zeroes the accumulators.
// ---------------------------------------------------------------------------
__global__ void __launch_bounds__(256)
sample_detect_kernel(const float* __restrict__ src_flow,
                     const float* __restrict__ trg_flow,
                     const float* __restrict__ src_kp,
                     const float* __restrict__ trg_kp,
                     const unsigned char* __restrict__ kp_vis) {
    if (blockIdx.x == 128) {
        // --- detection block ---
        __shared__ int cnt[4];
        int tid = threadIdx.x;
        if (tid < 4) cnt[tid] = 0;
        __syncthreads();
        const uint4* v4 = (const uint4*)kp_vis;      // 32768 bytes = 2048 uint4
        int c0 = 0, c1 = 0, c2 = 0, c3 = 0;
#pragma unroll
        for (int k = 0; k < 8; k++) {
            uint4 w = v4[tid + k * 256];
            unsigned int ws[4] = {w.x, w.y, w.z, w.w};
#pragma unroll
            for (int q = 0; q < 4; q++) {
                c0 += (ws[q] & 0x000000FFu) != 0;
                c1 += (ws[q] & 0x0000FF00u) != 0;
                c2 += (ws[q] & 0x00FF0000u) != 0;
                c3 += (ws[q] & 0xFF000000u) != 0;
            }
        }
        atomicAdd(&cnt[0], c0); atomicAdd(&cnt[1], c1);
        atomicAdd(&cnt[2], c2); atomicAdd(&cnt[3], c3);
        __syncthreads();
        if (tid == 0) {
            int r0 = cnt[0], r1 = cnt[1], r2 = cnt[2], r3 = cnt[3];
            int mode;
            if (r0 > 0 && r1 == 0 && r2 == 0 && r3 == 0)       mode = 1; // int32
            else if (r0 == 0 && r1 == 0 && (r2 > 0 || r3 > 0)) mode = 2; // float32
            else                                               mode = 0; // uint8
            g_vis_mode = mode;
            g_loss_acc = 0.f;
            g_vis_acc  = 0.f;
            g_done     = 0u;
        }
        return;
    }
    // --- sampling blocks ---
    int idx = blockIdx.x * blockDim.x + threadIdx.x;   // 0 .. 32767
    int n = idx >> 10;
    const float2* sf = (const float2*)src_flow + (size_t)n * RESO * RESO;
    const float2* tf = (const float2*)trg_flow + (size_t)n * RESO * RESO;
    float sx = src_kp[idx * 2 + 0], sy = src_kp[idx * 2 + 1];
    float tx = trg_kp[idx * 2 + 0], ty = trg_kp[idx * 2 + 1];
    g_src_c[idx] = bilin(sf, sx, sy);
    g_trg_c[idx] = bilin(tf, tx, ty);
}

// ---------------------------------------------------------------------------
// Kernel 2: per-column logsumexp + CE, weighted accumulate, fused finalize.
// grid = (KP/128, NB) = 256 blocks, block = 256 (128 columns x 2 i-splits)
// ---------------------------------------------------------------------------
__global__ void __launch_bounds__(256)
loss_kernel(const void* __restrict__ kp_vis,
            const float* __restrict__ kp_wt,
            float* __restrict__ out) {
    __shared__ float2 s_src[KP];      // 8 KB
    __shared__ float  s_part[256];    // 1 KB
    __shared__ float  s_c[8], s_v[8];

    int n   = blockIdx.y;
    int jt  = blockIdx.x;
    int tid = threadIdx.x;

    const float2* src = g_src_c + n * KP;
    for (int i = tid; i < KP; i += 256) s_src[i] = src[i];
    __syncthreads();

    int jl    = tid & 127;
    int split = tid >> 7;
    int j     = jt * 128 + jl;

    float2 t  = g_trg_c[n * KP + j];
    // dx = sx - tx + eps = sx + (-tx + eps)
    float2 tneg = make_float2(FEPS - t.x, FEPS - t.y);

    float S  = 0.f;
    int   i0 = split * (KP / 2);
#pragma unroll 8
    for (int i = i0; i < i0 + KP / 2; i++) {
        float2 d = fadd2(s_src[i], tneg);
        float d2 = fmaf(d.y, d.y, d.x * d.x);
        S += fex2_ap(NEG_L2E * fsqrt_ap(d2));
    }
    s_part[tid] = S;
    __syncthreads();

    float contrib = 0.f, v = 0.f;
    if (split == 0) {
        float Stot = s_part[jl] + s_part[jl + 128];
        float2 dj  = fadd2(s_src[j], tneg);
        float djj  = fsqrt_ap(fmaf(dj.y, dj.y, dj.x * dj.x));
        // ce_j = ln(S) + dist_jj ; forward d1 == d2 -> factor 2
        float ce = flg2_ap(Stot) * LN2F + djj;
        int idx = n * KP + j;
        int mode = g_vis_mode;
        float vv;
        if (mode == 0)      vv = ((const unsigned char*)kp_vis)[idx] ? 1.f : 0.f;
        else if (mode == 1) vv = ((const int*)kp_vis)[idx] ? 1.f : 0.f;
        else                vv = (((const float*)kp_vis)[idx] != 0.f) ? 1.f : 0.f;
        contrib = 2.f * ce * vv * kp_wt[idx];
        v = vv;
    }

    // block reduction
#pragma unroll
    for (int off = 16; off; off >>= 1) {
        contrib += __shfl_down_sync(0xffffffff, contrib, off);
        v       += __shfl_down_sync(0xffffffff, v, off);
    }
    int w = tid >> 5, l = tid & 31;
    if (l == 0) { s_c[w] = contrib; s_v[w] = v; }
    __syncthreads();
    if (tid == 0) {
        float c = 0.f, vs = 0.f;
#pragma unroll
        for (int k = 0; k < 8; k++) { c += s_c[k]; vs += s_v[k]; }
        atomicAdd(&g_loss_acc, c);
        atomicAdd(&g_vis_acc, vs);
        __threadfence();
        unsigned int ticket = atomicAdd(&g_done, 1u);
        if (ticket == LOSS_BLOCKS - 1) {
            // all 256 blocks' atomics are visible (fence + atomic ordering)
            float num = atomicAdd(&g_loss_acc, 0.f);
            float den = atomicAdd(&g_vis_acc, 0.f);
            out[0] = num / den;
        }
    }
}

extern "C" void kernel_launch(void* const* d_in, const int* in_sizes, int n_in,
                              void* d_out, int out_size) {
    const float* src_flow = (const float*)d_in[0];
    const float* trg_flow = (const float*)d_in[1];
    const float* src_kp   = (const float*)d_in[2];
    const float* trg_kp   = (const float*)d_in[3];
    const void*  kp_vis   = d_in[4];
    const float* kp_wt    = (const float*)d_in[5];
    float* out = (float*)d_out;

    sample_detect_kernel<<<129, 256>>>(src_flow, trg_flow, src_kp, trg_kp,
                                       (const unsigned char*)kp_vis);
    dim3 grid(KP / 128, NB);
    loss_kernel<<<grid, 256>>>(kp_vis, kp_wt, out);
}

// round 4
// speedup vs baseline: 1.5000x; 1.0835x over previous
#include <cuda_runtime.h>
#include <cuda_bf16.h>

// Problem constants
#define NB   32
#define RESO 256
#define KP   1024
#define FEPS 1e-6f
#define L2E  1.44269504088896340736f        // log2(e), T = 1
#define LN2F 0.69314718055994530942f

#define COLS_PER_BLK 32
#define SPLITS       8                       // 256 threads = 32 cols x 8 splits
#define ITERS        (KP / SPLITS)           // 128
#define LOSS_BLOCKS  (NB * (KP / COLS_PER_BLK))   // 1024

// Scratch (allocation-free rule: __device__ globals). Stored PRE-SCALED by L2E.
__device__ float2 g_src_c[NB * KP];
__device__ float2 g_trg_c[NB * KP];
__device__ float  g_loss_acc;
__device__ float  g_vis_acc;
__device__ int    g_vis_mode;                // 0 = uint8, 1 = int32, 2 = float32
__device__ unsigned int g_done = 0;

__device__ __forceinline__ float fsqrt_ap(float x) {
    float r; asm("sqrt.approx.f32 %0, %1;" : "=f"(r) : "f"(x)); return r;
}
__device__ __forceinline__ float fex2_ap(float x) {
    float r; asm("ex2.approx.f32 %0, %1;" : "=f"(r) : "f"(x)); return r;
}
__device__ __forceinline__ float flg2_ap(float x) {
    float r; asm("lg2.approx.f32 %0, %1;" : "=f"(r) : "f"(x)); return r;
}

// Bilinear sample with zero padding, align_corners=True pixel coords.
__device__ __forceinline__ float2 bilin(const float2* __restrict__ flow, float x, float y) {
    float x0f = floorf(x), y0f = floorf(y);
    int   x0  = (int)x0f,  y0  = (int)y0f;
    float wx = x - x0f, wy = y - y0f;
    float ax = 0.f, ay = 0.f;
#pragma unroll
    for (int dy = 0; dy < 2; dy++) {
#pragma unroll
        for (int dx = 0; dx < 2; dx++) {
            int xi = x0 + dx, yi = y0 + dy;
            float w = (dx ? wx : 1.f - wx) * (dy ? wy : 1.f - wy);
            if (xi >= 0 && xi < RESO && yi >= 0 && yi < RESO) {
                float2 v = __ldg(&flow[yi * RESO + xi]);
                ax = fmaf(w, v.x, ax);
                ay = fmaf(w, v.y, ay);
            }
        }
    }
    return make_float2(ax, ay);
}

// ---------------------------------------------------------------------------
// Kernel 1 (fused): blocks 0..127 bilinear-sample (values pre-scaled by L2E);
// block 128 detects kp_vis storage dtype and zeroes accumulators.
// ---------------------------------------------------------------------------
__global__ void __launch_bounds__(256)
sample_detect_kernel(const float* __restrict__ src_flow,
                     const float* __restrict__ trg_flow,
                     const float* __restrict__ src_kp,
                     const float* __restrict__ trg_kp,
                     const unsigned char* __restrict__ kp_vis) {
    if (blockIdx.x == 128) {
        // --- detection: nonzero-byte pattern per i%4 over first NB*KP bytes ---
        __shared__ int cnt[4];
        int tid = threadIdx.x;
        if (tid < 4) cnt[tid] = 0;
        __syncthreads();
        const uint4* v4 = (const uint4*)kp_vis;      // 32768 bytes = 2048 uint4
        int c0 = 0, c1 = 0, c2 = 0, c3 = 0;
#pragma unroll
        for (int k = 0; k < 8; k++) {
            uint4 w = v4[tid + k * 256];
            unsigned int ws[4] = {w.x, w.y, w.z, w.w};
#pragma unroll
            for (int q = 0; q < 4; q++) {
                c0 += (ws[q] & 0x000000FFu) != 0;
                c1 += (ws[q] & 0x0000FF00u) != 0;
                c2 += (ws[q] & 0x00FF0000u) != 0;
                c3 += (ws[q] & 0xFF000000u) != 0;
            }
        }
        atomicAdd(&cnt[0], c0); atomicAdd(&cnt[1], c1);
        atomicAdd(&cnt[2], c2); atomicAdd(&cnt[3], c3);
        __syncthreads();
        if (tid == 0) {
            int r0 = cnt[0], r1 = cnt[1], r2 = cnt[2], r3 = cnt[3];
            int mode;
            if (r0 > 0 && r1 == 0 && r2 == 0 && r3 == 0)       mode = 1; // int32
            else if (r0 == 0 && r1 == 0 && (r2 > 0 || r3 > 0)) mode = 2; // float32
            else                                               mode = 0; // uint8
            g_vis_mode = mode;
            g_loss_acc = 0.f;
            g_vis_acc  = 0.f;
            g_done     = 0u;
        }
        return;
    }
    // --- sampling blocks ---
    int idx = blockIdx.x * blockDim.x + threadIdx.x;   // 0 .. 32767
    int n = idx >> 10;
    const float2* sf = (const float2*)src_flow + (size_t)n * RESO * RESO;
    const float2* tf = (const float2*)trg_flow + (size_t)n * RESO * RESO;
    float sx = src_kp[idx * 2 + 0], sy = src_kp[idx * 2 + 1];
    float tx = trg_kp[idx * 2 + 0], ty = trg_kp[idx * 2 + 1];
    float2 s = bilin(sf, sx, sy);
    float2 t = bilin(tf, tx, ty);
    g_src_c[idx] = make_float2(s.x * L2E, s.y * L2E);
    g_trg_c[idx] = make_float2(t.x * L2E, t.y * L2E);
}

// ---------------------------------------------------------------------------
// Kernel 2: per-column logsumexp + CE in base-2 units, fused finalize.
// grid = (KP/32, NB) = 1024 blocks; block = 256 = 32 columns x 8 i-splits.
// Whole grid is resident in one wave (~7 CTAs/SM) -> no wave quantization.
// ---------------------------------------------------------------------------
__global__ void __launch_bounds__(256)
loss_kernel(const void* __restrict__ kp_vis,
            const float* __restrict__ kp_wt,
            float* __restrict__ out) {
    __shared__ float2 s_src[KP];      // 8 KB (scaled by L2E)
    __shared__ float  s_part[256];    // 1 KB

    int n   = blockIdx.y;
    int jt  = blockIdx.x;
    int tid = threadIdx.x;

    const float2* src = g_src_c + n * KP;
    for (int i = tid; i < KP; i += 256) s_src[i] = src[i];
    __syncthreads();

    int jl    = tid & (COLS_PER_BLK - 1);    // column within tile
    int split = tid >> 5;                    // 0..7 (warp id)
    int j     = jt * COLS_PER_BLK + jl;      // global column

    float2 t  = g_trg_c[n * KP + j];
    // d' = s' - t' + l2e*eps  (all in L2E-scaled units)
    float tnx = FEPS * L2E - t.x;
    float tny = FEPS * L2E - t.y;

    float S  = 0.f;
    int   i0 = split * ITERS;
#pragma unroll 8
    for (int i = i0; i < i0 + ITERS; i++) {
        float2 s = s_src[i];
        float dx = s.x + tnx;
        float dy = s.y + tny;
        float d2 = fmaf(dy, dy, dx * dx);
        S += fex2_ap(-fsqrt_ap(d2));         // exp(-dist): neg folds into MUFU
    }
    s_part[tid] = S;
    __syncthreads();

    // warp 0 (split==0) owns the 32 columns of this tile
    if (split == 0) {
        float Stot = 0.f;
#pragma unroll
        for (int k = 0; k < SPLITS; k++) Stot += s_part[jl + k * COLS_PER_BLK];
        float2 sj  = s_src[j];
        float dxj  = sj.x + tnx;
        float dyj  = sj.y + tny;
        float djj  = fsqrt_ap(fmaf(dyj, dyj, dxj * dxj));   // scaled dist
        // ce = ln(S) + dist = LN2 * (lg2(S) + d'jj); d1==d2 forward -> x2
        float ce = LN2F * (flg2_ap(Stot) + djj);
        int idx = n * KP + j;
        int mode = g_vis_mode;
        float vv;
        if (mode == 0)      vv = ((const unsigned char*)kp_vis)[idx] ? 1.f : 0.f;
        else if (mode == 1) vv = ((const int*)kp_vis)[idx] ? 1.f : 0.f;
        else                vv = (((const float*)kp_vis)[idx] != 0.f) ? 1.f : 0.f;
        float contrib = 2.f * ce * vv * kp_wt[idx];

#pragma unroll
        for (int off = 16; off; off >>= 1) {
            contrib += __shfl_down_sync(0xffffffff, contrib, off);
            vv      += __shfl_down_sync(0xffffffff, vv, off);
        }
        if (jl == 0) {
            atomicAdd(&g_loss_acc, contrib);
            atomicAdd(&g_vis_acc, vv);
            __threadfence();
            unsigned int ticket = atomicAdd(&g_done, 1u);
            if (ticket == LOSS_BLOCKS - 1) {
                float num = atomicAdd(&g_loss_acc, 0.f);
                float den = atomicAdd(&g_vis_acc, 0.f);
                out[0] = num / den;
            }
        }
    }
}

extern "C" void kernel_launch(void* const* d_in, const int* in_sizes, int n_in,
                              void* d_out, int out_size) {
    const float* src_flow = (const float*)d_in[0];
    const float* trg_flow = (const float*)d_in[1];
    const float* src_kp   = (const float*)d_in[2];
    const float* trg_kp   = (const float*)d_in[3];
    const void*  kp_vis   = d_in[4];
    const float* kp_wt    = (const float*)d_in[5];
    float* out = (float*)d_out;

    sample_detect_kernel<<<129, 256>>>(src_flow, trg_flow, src_kp, trg_kp,
                                       (const unsigned char*)kp_vis);
    dim3 grid(KP / COLS_PER_BLK, NB);
    loss_kernel<<<grid, 256>>>(kp_vis, kp_wt, out);
}

// round 5
// speedup vs baseline: 1.6300x; 1.0867x over previous
#include <cuda_runtime.h>
#include <cuda_fp16.h>
#include <cuda_bf16.h>

// Problem constants
#define NB   32
#define RESO 256
#define KP   1024
#define FEPS 1e-6f
#define L2E  1.44269504088896340736f        // log2(e), T = 1
#define LN2F 0.69314718055994530942f

#define COLS_PER_BLK 32
#define SPLITS       8                       // 256 threads = 32 cols x 8 splits
#define ITERS        (KP / SPLITS)           // 128 pairs per thread
#define LOSS_BLOCKS  (NB * (KP / COLS_PER_BLK))   // 1024

// Scratch (allocation-free rule: __device__ globals). Stored PRE-SCALED by L2E.
__device__ float2 g_src_c[NB * KP];
__device__ float2 g_trg_c[NB * KP];
__device__ float  g_loss_acc;
__device__ float  g_vis_acc;
__device__ int    g_vis_mode;                // 0 = uint8, 1 = int32, 2 = float32
__device__ unsigned int g_done = 0;

__device__ __forceinline__ float fsqrt_ap(float x) {
    float r; asm("sqrt.approx.f32 %0, %1;" : "=f"(r) : "f"(x)); return r;
}
__device__ __forceinline__ float frsq_ap(float x) {
    float r; asm("rsqrt.approx.f32 %0, %1;" : "=f"(r) : "f"(x)); return r;
}
__device__ __forceinline__ float flg2_ap(float x) {
    float r; asm("lg2.approx.f32 %0, %1;" : "=f"(r) : "f"(x)); return r;
}
// pack two f32 into f16x2 and take 2^x on both halves with ONE MUFU op
__device__ __forceinline__ __half2 ex2_pack(float a, float b) {
    unsigned int ru;
    asm("{\n\t.reg .b32 t;\n\t"
        "cvt.rn.f16x2.f32 t, %1, %2;\n\t"
        "ex2.approx.f16x2 %0, t;\n\t}"
        : "=r"(ru) : "f"(a), "f"(b));
    return *reinterpret_cast<__half2*>(&ru);
}

// Bilinear sample with zero padding, align_corners=True pixel coords.
__device__ __forceinline__ float2 bilin(const float2* __restrict__ flow, float x, float y) {
    float x0f = floorf(x), y0f = floorf(y);
    int   x0  = (int)x0f,  y0  = (int)y0f;
    float wx = x - x0f, wy = y - y0f;
    float ax = 0.f, ay = 0.f;
#pragma unroll
    for (int dy = 0; dy < 2; dy++) {
#pragma unroll
        for (int dx = 0; dx < 2; dx++) {
            int xi = x0 + dx, yi = y0 + dy;
            float w = (dx ? wx : 1.f - wx) * (dy ? wy : 1.f - wy);
            if (xi >= 0 && xi < RESO && yi >= 0 && yi < RESO) {
                float2 v = __ldg(&flow[yi * RESO + xi]);
                ax = fmaf(w, v.x, ax);
                ay = fmaf(w, v.y, ay);
            }
        }
    }
    return make_float2(ax, ay);
}

// ---------------------------------------------------------------------------
// Kernel 1 (fused): blocks 0..127 bilinear-sample (values pre-scaled by L2E);
// block 128 detects kp_vis storage dtype and zeroes accumulators.
// ---------------------------------------------------------------------------
__global__ void __launch_bounds__(256)
sample_detect_kernel(const float* __restrict__ src_flow,
                     const float* __restrict__ trg_flow,
                     const float* __restrict__ src_kp,
                     const float* __restrict__ trg_kp,
                     const unsigned char* __restrict__ kp_vis) {
    if (blockIdx.x == 128) {
        // --- detection: nonzero-byte pattern per i%4 over first NB*KP bytes ---
        __shared__ int cnt[4];
        int tid = threadIdx.x;
        if (tid < 4) cnt[tid] = 0;
        __syncthreads();
        const uint4* v4 = (const uint4*)kp_vis;      // 32768 bytes = 2048 uint4
        int c0 = 0, c1 = 0, c2 = 0, c3 = 0;
#pragma unroll
        for (int k = 0; k < 8; k++) {
            uint4 w = v4[tid + k * 256];
            unsigned int ws[4] = {w.x, w.y, w.z, w.w};
#pragma unroll
            for (int q = 0; q < 4; q++) {
                c0 += (ws[q] & 0x000000FFu) != 0;
                c1 += (ws[q] & 0x0000FF00u) != 0;
                c2 += (ws[q] & 0x00FF0000u) != 0;
                c3 += (ws[q] & 0xFF000000u) != 0;
            }
        }
        atomicAdd(&cnt[0], c0); atomicAdd(&cnt[1], c1);
        atomicAdd(&cnt[2], c2); atomicAdd(&cnt[3], c3);
        __syncthreads();
        if (tid == 0) {
            int r0 = cnt[0], r1 = cnt[1], r2 = cnt[2], r3 = cnt[3];
            int mode;
            if (r0 > 0 && r1 == 0 && r2 == 0 && r3 == 0)       mode = 1; // int32
            else if (r0 == 0 && r1 == 0 && (r2 > 0 || r3 > 0)) mode = 2; // float32
            else                                               mode = 0; // uint8
            g_vis_mode = mode;
            g_loss_acc = 0.f;
            g_vis_acc  = 0.f;
            g_done     = 0u;
        }
        return;
    }
    // --- sampling blocks ---
    int idx = blockIdx.x * blockDim.x + threadIdx.x;   // 0 .. 32767
    int n = idx >> 10;
    const float2* sf = (const float2*)src_flow + (size_t)n * RESO * RESO;
    const float2* tf = (const float2*)trg_flow + (size_t)n * RESO * RESO;
    float sx = src_kp[idx * 2 + 0], sy = src_kp[idx * 2 + 1];
    float tx = trg_kp[idx * 2 + 0], ty = trg_kp[idx * 2 + 1];
    float2 s = bilin(sf, sx, sy);
    float2 t = bilin(tf, tx, ty);
    g_src_c[idx] = make_float2(s.x * L2E, s.y * L2E);
    g_trg_c[idx] = make_float2(t.x * L2E, t.y * L2E);
}

// -d' for one pair, in L2E-scaled units:  -d2 * rsqrt(d2)  (neg folds in FMUL)
__device__ __forceinline__ float neg_dist(float2 s, float tnx, float tny) {
    float dx = s.x + tnx;
    float dy = s.y + tny;
    float d2 = fmaf(dy, dy, fmaf(dx, dx, 1e-30f));   // bias: rsq never sees 0
    return (-d2) * frsq_ap(d2);
}

// ---------------------------------------------------------------------------
// Kernel 2: per-column logsumexp + CE in base-2 units, fused finalize.
// grid = (KP/32, NB) = 1024 blocks; block = 256 = 32 columns x 8 i-splits.
// Inner loop: 2 pairs/step, ONE MUFU ex2.f16x2 for both exponentials.
// ---------------------------------------------------------------------------
__global__ void __launch_bounds__(256)
loss_kernel(const void* __restrict__ kp_vis,
            const float* __restrict__ kp_wt,
            float* __restrict__ out) {
    __shared__ float2 s_src[KP];      // 8 KB (scaled by L2E)
    __shared__ float  s_part[256];    // 1 KB

    int n   = blockIdx.y;
    int jt  = blockIdx.x;
    int tid = threadIdx.x;

    const float2* src = g_src_c + n * KP;
    for (int i = tid; i < KP; i += 256) s_src[i] = src[i];
    __syncthreads();

    int jl    = tid & (COLS_PER_BLK - 1);    // column within tile
    int split = tid >> 5;                    // 0..7 (warp id)
    int j     = jt * COLS_PER_BLK + jl;      // global column

    float2 t  = g_trg_c[n * KP + j];
    float tnx = FEPS * L2E - t.x;            // d = s - t + eps (scaled units)
    float tny = FEPS * L2E - t.y;

    float S  = 0.f;
    int   i0 = split * ITERS;
    // 128 pairs = 16 flush groups x 4 steps x 2 pairs
#pragma unroll 4
    for (int g = 0; g < ITERS / 8; g++) {
        __half2 hacc = __float2half2_rn(0.f);
#pragma unroll
        for (int k = 0; k < 4; k++) {
            int i = i0 + g * 8 + k * 2;
            float nd0 = neg_dist(s_src[i],     tnx, tny);
            float nd1 = neg_dist(s_src[i + 1], tnx, tny);
            hacc = __hadd2(hacc, ex2_pack(nd0, nd1));
        }
        float2 f = __half22float2(hacc);     // flush: half-sums <= 4, low error
        S += f.x + f.y;
    }
    s_part[tid] = S;
    __syncthreads();

    // warp 0 (split==0) owns the 32 columns of this tile
    if (split == 0) {
        float Stot = 0.f;
#pragma unroll
        for (int k = 0; k < SPLITS; k++) Stot += s_part[jl + k * COLS_PER_BLK];
        float2 sj  = s_src[j];
        float dxj  = sj.x + tnx;
        float dyj  = sj.y + tny;
        float djj  = fsqrt_ap(fmaf(dyj, dyj, dxj * dxj));   // scaled dist (f32)
        // ce = ln(S) + dist = LN2 * (lg2(S) + d'jj); d1==d2 forward -> x2
        float ce = LN2F * (flg2_ap(Stot) + djj);
        int idx = n * KP + j;
        int mode = g_vis_mode;
        float vv;
        if (mode == 0)      vv = ((const unsigned char*)kp_vis)[idx] ? 1.f : 0.f;
        else if (mode == 1) vv = ((const int*)kp_vis)[idx] ? 1.f : 0.f;
        else                vv = (((const float*)kp_vis)[idx] != 0.f) ? 1.f : 0.f;
        float contrib = 2.f * ce * vv * kp_wt[idx];

#pragma unroll
        for (int off = 16; off; off >>= 1) {
            contrib += __shfl_down_sync(0xffffffff, contrib, off);
            vv      += __shfl_down_sync(0xffffffff, vv, off);
        }
        if (jl == 0) {
            atomicAdd(&g_loss_acc, contrib);
            atomicAdd(&g_vis_acc, vv);
            __threadfence();
            unsigned int ticket = atomicAdd(&g_done, 1u);
            if (ticket == LOSS_BLOCKS - 1) {
                float num = atomicAdd(&g_loss_acc, 0.f);
                float den = atomicAdd(&g_vis_acc, 0.f);
                out[0] = num / den;
            }
        }
    }
}

extern "C" void kernel_launch(void* const* d_in, const int* in_sizes, int n_in,
                              void* d_out, int out_size) {
    const float* src_flow = (const float*)d_in[0];
    const float* trg_flow = (const float*)d_in[1];
    const float* src_kp   = (const float*)d_in[2];
    const float* trg_kp   = (const float*)d_in[3];
    const void*  kp_vis   = d_in[4];
    const float* kp_wt    = (const float*)d_in[5];
    float* out = (float*)d_out;

    sample_detect_kernel<<<129, 256>>>(src_flow, trg_flow, src_kp, trg_kp,
                                       (const unsigned char*)kp_vis);
    dim3 grid(KP / COLS_PER_BLK, NB);
    loss_kernel<<<grid, 256>>>(kp_vis, kp_wt, out);
}